// round 9
// baseline (speedup 1.0000x reference)
#include <cuda_runtime.h>
#include <cuda_fp16.h>
#include <cstdint>

#define NROWS 16384
#define NF    256

// ---------------- scratch (no allocations allowed) ----------------
__device__ __half g_xcat[NROWS * 768];     // [x_hi | x_hi | x_lo] per row
__device__ __half g_wcat[128 * 768];       // [w1_hi | w1_lo | w1_hi] per out
__device__ __half g_wp2h[128 * 256];       // Wp[:,256:512] fp16
__device__ __half g_yTh[128 * NROWS];      // yT = Wp2h @ x^T  [128][16384]
__device__ float  g_xp[NROWS * 128];       // x @ Wp1^T (split-fp16 accurate)

// ---------------- helpers ----------------
__device__ __forceinline__ void cp16(uint32_t saddr, const void* gaddr) {
    asm volatile("cp.async.cg.shared.global [%0], [%1], 16;"
                 :: "r"(saddr), "l"(gaddr));
}
__device__ __forceinline__ uint32_t cvta_smem(const void* p) {
    uint32_t a;
    asm("{ .reg .u64 t; cvta.to.shared.u64 t, %1; cvt.u32.u64 %0, t; }"
        : "=r"(a) : "l"(p));
    return a;
}
__device__ __forceinline__ void mma_f16(float& d0, float& d1, float& d2, float& d3,
                                        uint32_t a0, uint32_t a1, uint32_t a2, uint32_t a3,
                                        uint32_t b0, uint32_t b1) {
    asm volatile(
        "mma.sync.aligned.m16n8k16.row.col.f32.f16.f16.f32 "
        "{%0,%1,%2,%3}, {%4,%5,%6,%7}, {%8,%9}, {%0,%1,%2,%3};"
        : "+f"(d0), "+f"(d1), "+f"(d2), "+f"(d3)
        : "r"(a0), "r"(a1), "r"(a2), "r"(a3), "r"(b0), "r"(b1));
}
__device__ __forceinline__ uint32_t h2u(__half2 h) {
    return *reinterpret_cast<uint32_t*>(&h);
}

// ================= P1: conversions =================
__global__ __launch_bounds__(256)
void convert_x(const float* __restrict__ x) {
    int idx = blockIdx.x * 256 + threadIdx.x;   // 1,048,576 total
    int row = idx >> 6;
    int c   = (idx & 63) * 4;
    float4 v = *reinterpret_cast<const float4*>(x + (size_t)row * NF + c);
    __half hx = __float2half_rn(v.x), hy = __float2half_rn(v.y);
    __half hz = __float2half_rn(v.z), hw = __float2half_rn(v.w);
    __half lx = __float2half_rn(v.x - __half2float(hx));
    __half ly = __float2half_rn(v.y - __half2float(hy));
    __half lz = __float2half_rn(v.z - __half2float(hz));
    __half lw = __float2half_rn(v.w - __half2float(hw));
    __half2* base = reinterpret_cast<__half2*>(g_xcat + (size_t)row * 768);
    __half2 h01; h01.x = hx; h01.y = hy;
    __half2 h23; h23.x = hz; h23.y = hw;
    __half2 l01; l01.x = lx; l01.y = ly;
    __half2 l23; l23.x = lz; l23.y = lw;
    base[c / 2]             = h01;  base[c / 2 + 1]             = h23;
    base[(256 + c) / 2]     = h01;  base[(256 + c) / 2 + 1]     = h23;
    base[(512 + c) / 2]     = l01;  base[(512 + c) / 2 + 1]     = l23;
}

__global__ __launch_bounds__(256)
void convert_w(const float* __restrict__ Wp) {
    int idx = blockIdx.x * 256 + threadIdx.x;   // 65536 total
    int n = idx >> 9, c = idx & 511;
    float v = Wp[idx];
    __half h = __float2half_rn(v);
    if (c < 256) {
        __half l = __float2half_rn(v - __half2float(h));
        g_wcat[n * 768 + c]       = h;
        g_wcat[n * 768 + 256 + c] = l;
        g_wcat[n * 768 + 512 + c] = h;
    } else {
        g_wp2h[n * 256 + (c - 256)] = h;
    }
}

// ================= P2: yT = Wp2h @ x^T  (C [128][16384] fp16) =========
// grid 128 CTAs (128 node-cols each), 256 threads, 8 warps: 2M x 4N, warp 64x32.
#define P_AST 2560           // 128 rows * 20 u32
__device__ __forceinline__ void p_load(uint32_t dst, const __half* src,
                                       int pitch, int k0, int tid) {
#pragma unroll
    for (int j = 0; j < 2; j++) {
        int q = tid + 256 * j;
        int r = q >> 2, cc = q & 3;
        cp16(dst + r * 80 + cc * 16, src + (size_t)r * pitch + k0 + cc * 8);
    }
}

__global__ __launch_bounds__(256)
void p2_yT() {
    extern __shared__ uint32_t sm2[];
    const int tid = threadIdx.x, wid = tid >> 5, lane = tid & 31;
    const int lq = lane >> 2, lr = lane & 3;
    const int wm = wid & 1, wn = wid >> 1;
    const int n0 = blockIdx.x * 128;
    uint32_t abase = cvta_smem(sm2);
    uint32_t bbase = abase + 2 * P_AST * 4;

    float acc[4][4][4];
#pragma unroll
    for (int i = 0; i < 4; i++)
#pragma unroll
        for (int j = 0; j < 4; j++)
#pragma unroll
            for (int v = 0; v < 4; v++) acc[i][j][v] = 0.f;

#pragma unroll
    for (int s = 0; s < 2; s++) {
        p_load(abase + s * P_AST * 4, g_wp2h, 256, s * 32, tid);
        p_load(bbase + s * P_AST * 4, g_xcat + (size_t)n0 * 768, 768, s * 32, tid);
        asm volatile("cp.async.commit_group;" ::: "memory");
    }
    const int NI = 8;
#pragma unroll 1
    for (int i = 0; i < NI; i++) {
        int s = i & 1;
        if (i < NI - 1) asm volatile("cp.async.wait_group 1;" ::: "memory");
        else            asm volatile("cp.async.wait_group 0;" ::: "memory");
        __syncthreads();
        const uint32_t* As = sm2 + s * P_AST;
        const uint32_t* Bs = sm2 + 2 * P_AST + s * P_AST;
#pragma unroll
        for (int ks = 0; ks < 2; ks++) {
            uint32_t af[4][4];
#pragma unroll
            for (int mt = 0; mt < 4; mt++) {
                int b = (wm * 64 + mt * 16 + lq) * 20 + ks * 8 + lr;
                af[mt][0] = As[b]; af[mt][1] = As[b + 160];
                af[mt][2] = As[b + 4]; af[mt][3] = As[b + 164];
            }
            uint32_t bf[4][2];
#pragma unroll
            for (int nt = 0; nt < 4; nt++) {
                int b = (wn * 32 + nt * 8 + lq) * 20 + ks * 8 + lr;
                bf[nt][0] = Bs[b]; bf[nt][1] = Bs[b + 4];
            }
#pragma unroll
            for (int mt = 0; mt < 4; mt++)
#pragma unroll
                for (int nt = 0; nt < 4; nt++)
                    mma_f16(acc[mt][nt][0], acc[mt][nt][1], acc[mt][nt][2], acc[mt][nt][3],
                            af[mt][0], af[mt][1], af[mt][2], af[mt][3],
                            bf[nt][0], bf[nt][1]);
        }
        __syncthreads();
        if (i + 2 < NI) {
            p_load(abase + s * P_AST * 4, g_wp2h, 256, (i + 2) * 32, tid);
            p_load(bbase + s * P_AST * 4, g_xcat + (size_t)n0 * 768, 768, (i + 2) * 32, tid);
            asm volatile("cp.async.commit_group;" ::: "memory");
        }
    }
#pragma unroll
    for (int mt = 0; mt < 4; mt++)
#pragma unroll
        for (int nt = 0; nt < 4; nt++) {
            int r = wm * 64 + mt * 16 + lq;
            int n = n0 + wn * 32 + nt * 8 + lr * 2;
            __half2 v0; v0.x = __float2half_rn(acc[mt][nt][0]); v0.y = __float2half_rn(acc[mt][nt][1]);
            __half2 v1; v1.x = __float2half_rn(acc[mt][nt][2]); v1.y = __float2half_rn(acc[mt][nt][3]);
            *reinterpret_cast<__half2*>(g_yTh + (size_t)r * NROWS + n) = v0;
            *reinterpret_cast<__half2*>(g_yTh + (size_t)(r + 8) * NROWS + n) = v1;
        }
}

// ================= P3: xp = xcat @ wcat^T  (C [16384][128] fp32) =======
// grid 128 CTAs (128 rows each), 256 threads, 8 warps: 4M x 2N, warp 32x64.
__global__ __launch_bounds__(256)
void p3_xp() {
    extern __shared__ uint32_t sm3[];
    const int tid = threadIdx.x, wid = tid >> 5, lane = tid & 31;
    const int lq = lane >> 2, lr = lane & 3;
    const int wm = wid & 3, wn = wid >> 2;
    const int m0 = blockIdx.x * 128;
    uint32_t abase = cvta_smem(sm3);
    uint32_t bbase = abase + 2 * P_AST * 4;

    float acc[2][8][4];
#pragma unroll
    for (int i = 0; i < 2; i++)
#pragma unroll
        for (int j = 0; j < 8; j++)
#pragma unroll
            for (int v = 0; v < 4; v++) acc[i][j][v] = 0.f;

#pragma unroll
    for (int s = 0; s < 2; s++) {
        p_load(abase + s * P_AST * 4, g_xcat + (size_t)m0 * 768, 768, s * 32, tid);
        p_load(bbase + s * P_AST * 4, g_wcat, 768, s * 32, tid);
        asm volatile("cp.async.commit_group;" ::: "memory");
    }
    const int NI = 24;
#pragma unroll 1
    for (int i = 0; i < NI; i++) {
        int s = i & 1;
        if (i < NI - 1) asm volatile("cp.async.wait_group 1;" ::: "memory");
        else            asm volatile("cp.async.wait_group 0;" ::: "memory");
        __syncthreads();
        const uint32_t* As = sm3 + s * P_AST;
        const uint32_t* Bs = sm3 + 2 * P_AST + s * P_AST;
#pragma unroll
        for (int ks = 0; ks < 2; ks++) {
            uint32_t af[2][4];
#pragma unroll
            for (int mt = 0; mt < 2; mt++) {
                int b = (wm * 32 + mt * 16 + lq) * 20 + ks * 8 + lr;
                af[mt][0] = As[b]; af[mt][1] = As[b + 160];
                af[mt][2] = As[b + 4]; af[mt][3] = As[b + 164];
            }
            uint32_t bf[8][2];
#pragma unroll
            for (int nt = 0; nt < 8; nt++) {
                int b = (wn * 64 + nt * 8 + lq) * 20 + ks * 8 + lr;
                bf[nt][0] = Bs[b]; bf[nt][1] = Bs[b + 4];
            }
#pragma unroll
            for (int mt = 0; mt < 2; mt++)
#pragma unroll
                for (int nt = 0; nt < 8; nt++)
                    mma_f16(acc[mt][nt][0], acc[mt][nt][1], acc[mt][nt][2], acc[mt][nt][3],
                            af[mt][0], af[mt][1], af[mt][2], af[mt][3],
                            bf[nt][0], bf[nt][1]);
        }
        __syncthreads();
        if (i + 2 < NI) {
            p_load(abase + s * P_AST * 4, g_xcat + (size_t)m0 * 768, 768, (i + 2) * 32, tid);
            p_load(bbase + s * P_AST * 4, g_wcat, 768, (i + 2) * 32, tid);
            asm volatile("cp.async.commit_group;" ::: "memory");
        }
    }
#pragma unroll
    for (int mt = 0; mt < 2; mt++)
#pragma unroll
        for (int nt = 0; nt < 8; nt++) {
            int r = m0 + wm * 32 + mt * 16 + lq;
            int c = wn * 64 + nt * 8 + lr * 2;
            *reinterpret_cast<float2*>(g_xp + (size_t)r * 128 + c) =
                make_float2(acc[mt][nt][0], acc[mt][nt][1]);
            *reinterpret_cast<float2*>(g_xp + (size_t)(r + 8) * 128 + c) =
                make_float2(acc[mt][nt][2], acc[mt][nt][3]);
        }
}

// ================= Kernel Z: z = adj @ y, fused h/MLP/softmax epilogue ====
#define ZA_ST 2560            // 128 rows * 20 u32 (fp16 A stage)
#define ZB_ST 2560            // 128 n-rows * 20 u32
#define NIZ   512
// epilogue smem offsets (floats)
#define H_OFF   0             // 128 x 132
#define H1_OFF  16896         // 128 x 68
#define W1T_OFF 25600         // 128 x 64
#define H2_OFF  33792         // 128 x 36
#define W2T_OFF 38400         // 64 x 32
#define W3T_OFF 40448         // 32 x 8
#define LG_OFF  40704         // 128 x 8
#define DEG_OFF 41728         // 128
#define Z_SMEM_FLOATS 41856

__global__ __launch_bounds__(512, 1)
void gemm_z(const float* __restrict__ adj,
            const float* __restrict__ W1, const float* __restrict__ b1,
            const float* __restrict__ W2, const float* __restrict__ b2,
            const float* __restrict__ W3, const float* __restrict__ b3,
            float* __restrict__ out) {
    extern __shared__ uint32_t smz[];
    uint32_t* Abuf = smz;
    uint32_t* Bbuf = smz + 2 * ZA_ST;
    float* pool = reinterpret_cast<float*>(smz);

    const int tid = threadIdx.x, wid = tid >> 5, lane = tid & 31;
    const int lq = lane >> 2, lr = lane & 3;
    const int gg = lane >> 3, cc = lane & 7;
    const int wm = wid & 3, wn = wid >> 2;      // 4M x 4N warps, tile 32x32
    const int m0 = blockIdx.x * 128;
    const uint32_t bbase = cvta_smem(Bbuf);

    float acc[2][4][4];
#pragma unroll
    for (int i = 0; i < 2; i++)
#pragma unroll
        for (int j = 0; j < 4; j++)
#pragma unroll
            for (int v = 0; v < 4; v++) acc[i][j][v] = 0.f;

    // B prologue (3 stages)
#pragma unroll
    for (int s = 0; s < 3; s++) {
        int n = tid >> 2, c4 = tid & 3;
        cp16(bbase + s * (ZB_ST * 4) + n * 80 + c4 * 16,
             g_yTh + (size_t)n * NROWS + s * 32 + c4 * 8);
        asm volatile("cp.async.commit_group;" ::: "memory");
    }

    const int rowA0 = wid * 8 + gg;
    float4 areg[2];
#pragma unroll
    for (int p = 0; p < 2; p++)
        areg[p] = *reinterpret_cast<const float4*>(
            adj + (size_t)(m0 + rowA0 + p * 4) * NROWS + cc * 4);
    float degp[2] = {0.f, 0.f};

#pragma unroll 1
    for (int i = 0; i < NIZ; i++) {
        const int sA = i & 1;
        const int sB = i % 3;
#pragma unroll
        for (int p = 0; p < 2; p++) {
            float4 v = areg[p];
            degp[p] += (v.x + v.y) + (v.z + v.w);
            __half2 h0 = __floats2half2_rn(v.x, v.y);
            __half2 h1 = __floats2half2_rn(v.z, v.w);
            uint32_t* dst = Abuf + sA * ZA_ST + (rowA0 + p * 4) * 20 + cc * 2;
            dst[0] = h2u(h0);
            dst[1] = h2u(h1);
        }
        if (i + 1 < NIZ) {
            int k0n = (i + 1) * 32;
#pragma unroll
            for (int p = 0; p < 2; p++)
                areg[p] = *reinterpret_cast<const float4*>(
                    adj + (size_t)(m0 + rowA0 + p * 4) * NROWS + k0n + cc * 4);
        }
        int rem = (NIZ - 1) - i;
        if (rem >= 2)      asm volatile("cp.async.wait_group 2;" ::: "memory");
        else if (rem == 1) asm volatile("cp.async.wait_group 1;" ::: "memory");
        else               asm volatile("cp.async.wait_group 0;" ::: "memory");
        __syncthreads();

        const uint32_t* As = Abuf + sA * ZA_ST;
        const uint32_t* Bs = Bbuf + sB * ZB_ST;
#pragma unroll
        for (int ks = 0; ks < 2; ks++) {
            uint32_t af[2][4];
#pragma unroll
            for (int mt = 0; mt < 2; mt++) {
                int b = (wm * 32 + mt * 16 + lq) * 20 + ks * 8 + lr;
                af[mt][0] = As[b]; af[mt][1] = As[b + 160];
                af[mt][2] = As[b + 4]; af[mt][3] = As[b + 164];
            }
            uint32_t bf[4][2];
#pragma unroll
            for (int nt = 0; nt < 4; nt++) {
                int b = (wn * 32 + nt * 8 + lq) * 20 + ks * 8 + lr;
                bf[nt][0] = Bs[b]; bf[nt][1] = Bs[b + 4];
            }
#pragma unroll
            for (int mt = 0; mt < 2; mt++)
#pragma unroll
                for (int nt = 0; nt < 4; nt++)
                    mma_f16(acc[mt][nt][0], acc[mt][nt][1], acc[mt][nt][2], acc[mt][nt][3],
                            af[mt][0], af[mt][1], af[mt][2], af[mt][3],
                            bf[nt][0], bf[nt][1]);
        }
        __syncthreads();
        if (i + 3 < NIZ) {
            int sN = (i + 3) % 3;
            int n = tid >> 2, c4 = tid & 3;
            cp16(bbase + sN * (ZB_ST * 4) + n * 80 + c4 * 16,
                 g_yTh + (size_t)n * NROWS + (i + 3) * 32 + c4 * 8);
            asm volatile("cp.async.commit_group;" ::: "memory");
        }
    }

    // ---- deg to smem ----
#pragma unroll
    for (int p = 0; p < 2; p++) {
        float d = degp[p];
#pragma unroll
        for (int off = 1; off < 8; off <<= 1)
            d += __shfl_xor_sync(0xffffffffu, d, off);
        if (cc == 0) pool[DEG_OFF + rowA0 + p * 4] = d + 1.0f;
    }
    __syncthreads();

    // ---- h = relu(xp + z/deg) -> smem ----
#pragma unroll
    for (int mt = 0; mt < 2; mt++) {
        int r = wm * 32 + mt * 16 + lq;
        float inv0 = 1.0f / pool[DEG_OFF + r];
        float inv1 = 1.0f / pool[DEG_OFF + r + 8];
#pragma unroll
        for (int nt = 0; nt < 4; nt++) {
            int c = wn * 32 + nt * 8 + lr * 2;
            float2 x0 = *reinterpret_cast<const float2*>(g_xp + (size_t)(m0 + r) * 128 + c);
            float2 x1 = *reinterpret_cast<const float2*>(g_xp + (size_t)(m0 + r + 8) * 128 + c);
            pool[H_OFF + r * 132 + c]           = fmaxf(x0.x + acc[mt][nt][0] * inv0, 0.f);
            pool[H_OFF + r * 132 + c + 1]       = fmaxf(x0.y + acc[mt][nt][1] * inv0, 0.f);
            pool[H_OFF + (r + 8) * 132 + c]     = fmaxf(x1.x + acc[mt][nt][2] * inv1, 0.f);
            pool[H_OFF + (r + 8) * 132 + c + 1] = fmaxf(x1.y + acc[mt][nt][3] * inv1, 0.f);
        }
    }
    // stage W1T/W2T/W3T
    for (int idx = tid; idx < 8192; idx += 512) {
        int j = idx >> 7, k = idx & 127;
        pool[W1T_OFF + k * 64 + j] = W1[idx];
    }
    for (int idx = tid; idx < 2048; idx += 512) {
        int j = idx >> 6, k = idx & 63;
        pool[W2T_OFF + k * 32 + j] = W2[idx];
    }
    if (tid < 256) {
        int j = tid >> 5, k = tid & 31;
        pool[W3T_OFF + k * 8 + j] = W3[tid];
    }
    __syncthreads();

    // ---- MLP1: h1 = lrelu(h @ W1^T + b1)  (128x64) ----
    {
        const int jg = tid & 15, rg = tid >> 4;    // 4 j x 4 r per thread
        float a[4][4];
#pragma unroll
        for (int jj = 0; jj < 4; jj++) {
            float bb = b1[jg * 4 + jj];
#pragma unroll
            for (int ri = 0; ri < 4; ri++) a[ri][jj] = bb;
        }
#pragma unroll 4
        for (int k = 0; k < 128; k++) {
            float4 wv = *reinterpret_cast<const float4*>(&pool[W1T_OFF + k * 64 + jg * 4]);
#pragma unroll
            for (int ri = 0; ri < 4; ri++) {
                float hv = pool[H_OFF + (rg * 4 + ri) * 132 + k];
                a[ri][0] += hv * wv.x; a[ri][1] += hv * wv.y;
                a[ri][2] += hv * wv.z; a[ri][3] += hv * wv.w;
            }
        }
#pragma unroll
        for (int ri = 0; ri < 4; ri++)
#pragma unroll
            for (int jj = 0; jj < 4; jj++) {
                float v = a[ri][jj];
                pool[H1_OFF + (rg * 4 + ri) * 68 + jg * 4 + jj] = (v > 0.f) ? v : 0.01f * v;
            }
    }
    __syncthreads();

    // ---- MLP2: h2 = lrelu(h1 @ W2^T + b2) (128x32) ----
#pragma unroll
    for (int ii = 0; ii < 8; ii++) {
        int o = tid + 512 * ii;
        int r = o >> 5, j = o & 31;
        float a = b2[j];
#pragma unroll 8
        for (int k = 0; k < 64; k++)
            a += pool[H1_OFF + r * 68 + k] * pool[W2T_OFF + k * 32 + j];
        pool[H2_OFF + r * 36 + j] = (a > 0.f) ? a : 0.01f * a;
    }
    __syncthreads();

    // ---- MLP3: logits (128x8) ----
#pragma unroll
    for (int ii = 0; ii < 2; ii++) {
        int o = tid + 512 * ii;
        int r = o >> 3, j = o & 7;
        float a = b3[j];
#pragma unroll
        for (int k = 0; k < 32; k++)
            a += pool[H2_OFF + r * 36 + k] * pool[W3T_OFF + k * 8 + j];
        pool[LG_OFF + r * 8 + j] = (a > 0.f) ? a : 0.01f * a;
    }
    __syncthreads();

    // ---- softmax + write ----
    if (tid < 128) {
        int r = tid;
        float vv[8], m = -1e30f;
#pragma unroll
        for (int c = 0; c < 8; c++) {
            vv[c] = pool[LG_OFF + r * 8 + c];
            m = fmaxf(m, vv[c]);
        }
        float s = 0.f;
#pragma unroll
        for (int c = 0; c < 8; c++) { vv[c] = expf(vv[c] - m); s += vv[c]; }
        float inv = 1.0f / s;
        float4 o0 = make_float4(vv[0] * inv, vv[1] * inv, vv[2] * inv, vv[3] * inv);
        float4 o1 = make_float4(vv[4] * inv, vv[5] * inv, vv[6] * inv, vv[7] * inv);
        *reinterpret_cast<float4*>(out + (size_t)(m0 + r) * 8)     = o0;
        *reinterpret_cast<float4*>(out + (size_t)(m0 + r) * 8 + 4) = o1;
    }
}

// ---------------- launch ----------------
extern "C" void kernel_launch(void* const* d_in, const int* in_sizes, int n_in,
                              void* d_out, int out_size) {
    const float* x   = (const float*)d_in[0];
    const float* adj = (const float*)d_in[1];
    const float* Wp  = (const float*)d_in[2];
    const float* W1  = (const float*)d_in[3];
    const float* b1  = (const float*)d_in[4];
    const float* W2  = (const float*)d_in[5];
    const float* b2  = (const float*)d_in[6];
    const float* W3  = (const float*)d_in[7];
    const float* b3  = (const float*)d_in[8];
    float* out = (float*)d_out;

    const int psm = 4 * P_AST * 4;                  // 40960
    const int zsm = Z_SMEM_FLOATS * 4;              // 167424
    cudaFuncSetAttribute(p2_yT, cudaFuncAttributeMaxDynamicSharedMemorySize, psm);
    cudaFuncSetAttribute(p3_xp, cudaFuncAttributeMaxDynamicSharedMemorySize, psm);
    cudaFuncSetAttribute(gemm_z, cudaFuncAttributeMaxDynamicSharedMemorySize, zsm);

    convert_x<<<4096, 256>>>(x);
    convert_w<<<256, 256>>>(Wp);
    p2_yT<<<128, 256, psm>>>();
    p3_xp<<<128, 256, psm>>>();
    gemm_z<<<128, 512, zsm>>>(adj, W1, b1, W2, b2, W3, b3, out);
}

// round 10
// speedup vs baseline: 1.3803x; 1.3803x over previous
#include <cuda_runtime.h>
#include <cuda_fp16.h>
#include <cstdint>

#define NROWS 16384
#define NF    256

// ---------------- scratch (no allocations allowed) ----------------
__device__ __half g_xcat[NROWS * 768];     // [x_hi | x_hi | x_lo] per row
__device__ __half g_wcat[128 * 768];       // [w1_hi | w1_lo | w1_hi] per out
__device__ __half g_wp2h[128 * 256];       // Wp[:,256:512] fp16
__device__ __half g_yTh[128 * NROWS];      // yT = Wp2h @ x^T  [128][16384]
__device__ float  g_xp[NROWS * 128];       // x @ Wp1^T (split-fp16 accurate)

// ---------------- helpers ----------------
__device__ __forceinline__ void cp16(uint32_t saddr, const void* gaddr) {
    asm volatile("cp.async.cg.shared.global [%0], [%1], 16;"
                 :: "r"(saddr), "l"(gaddr));
}
__device__ __forceinline__ uint32_t cvta_smem(const void* p) {
    uint32_t a;
    asm("{ .reg .u64 t; cvta.to.shared.u64 t, %1; cvt.u32.u64 %0, t; }"
        : "=r"(a) : "l"(p));
    return a;
}
__device__ __forceinline__ void mma_f16(float& d0, float& d1, float& d2, float& d3,
                                        uint32_t a0, uint32_t a1, uint32_t a2, uint32_t a3,
                                        uint32_t b0, uint32_t b1) {
    asm volatile(
        "mma.sync.aligned.m16n8k16.row.col.f32.f16.f16.f32 "
        "{%0,%1,%2,%3}, {%4,%5,%6,%7}, {%8,%9}, {%0,%1,%2,%3};"
        : "+f"(d0), "+f"(d1), "+f"(d2), "+f"(d3)
        : "r"(a0), "r"(a1), "r"(a2), "r"(a3), "r"(b0), "r"(b1));
}
__device__ __forceinline__ uint32_t h2u(__half2 h) {
    return *reinterpret_cast<uint32_t*>(&h);
}

// ================= P1: conversions =================
__global__ __launch_bounds__(256)
void convert_x(const float* __restrict__ x) {
    int idx = blockIdx.x * 256 + threadIdx.x;   // 1,048,576 total
    int row = idx >> 6;
    int c   = (idx & 63) * 4;
    float4 v = *reinterpret_cast<const float4*>(x + (size_t)row * NF + c);
    __half hx = __float2half_rn(v.x), hy = __float2half_rn(v.y);
    __half hz = __float2half_rn(v.z), hw = __float2half_rn(v.w);
    __half lx = __float2half_rn(v.x - __half2float(hx));
    __half ly = __float2half_rn(v.y - __half2float(hy));
    __half lz = __float2half_rn(v.z - __half2float(hz));
    __half lw = __float2half_rn(v.w - __half2float(hw));
    __half2* base = reinterpret_cast<__half2*>(g_xcat + (size_t)row * 768);
    __half2 h01; h01.x = hx; h01.y = hy;
    __half2 h23; h23.x = hz; h23.y = hw;
    __half2 l01; l01.x = lx; l01.y = ly;
    __half2 l23; l23.x = lz; l23.y = lw;
    base[c / 2]             = h01;  base[c / 2 + 1]             = h23;
    base[(256 + c) / 2]     = h01;  base[(256 + c) / 2 + 1]     = h23;
    base[(512 + c) / 2]     = l01;  base[(512 + c) / 2 + 1]     = l23;
}

__global__ __launch_bounds__(256)
void convert_w(const float* __restrict__ Wp) {
    int idx = blockIdx.x * 256 + threadIdx.x;   // 65536 total
    int n = idx >> 9, c = idx & 511;
    float v = Wp[idx];
    __half h = __float2half_rn(v);
    if (c < 256) {
        __half l = __float2half_rn(v - __half2float(h));
        g_wcat[n * 768 + c]       = h;
        g_wcat[n * 768 + 256 + c] = l;
        g_wcat[n * 768 + 512 + c] = h;
    } else {
        g_wp2h[n * 256 + (c - 256)] = h;
    }
}

// ================= P2: yT = Wp2h @ x^T  (C [128][16384] fp16) =========
// grid 128 CTAs (128 node-cols each), 256 threads, 8 warps: 2M x 4N, warp 64x32.
#define P_AST 2560           // 128 rows * 20 u32
__device__ __forceinline__ void p_load(uint32_t dst, const __half* src,
                                       int pitch, int k0, int tid) {
#pragma unroll
    for (int j = 0; j < 2; j++) {
        int q = tid + 256 * j;
        int r = q >> 2, cc = q & 3;
        cp16(dst + r * 80 + cc * 16, src + (size_t)r * pitch + k0 + cc * 8);
    }
}

__global__ __launch_bounds__(256)
void p2_yT() {
    extern __shared__ uint32_t sm2[];
    const int tid = threadIdx.x, wid = tid >> 5, lane = tid & 31;
    const int lq = lane >> 2, lr = lane & 3;
    const int wm = wid & 1, wn = wid >> 1;
    const int n0 = blockIdx.x * 128;
    uint32_t abase = cvta_smem(sm2);
    uint32_t bbase = abase + 2 * P_AST * 4;

    float acc[4][4][4];
#pragma unroll
    for (int i = 0; i < 4; i++)
#pragma unroll
        for (int j = 0; j < 4; j++)
#pragma unroll
            for (int v = 0; v < 4; v++) acc[i][j][v] = 0.f;

#pragma unroll
    for (int s = 0; s < 2; s++) {
        p_load(abase + s * P_AST * 4, g_wp2h, 256, s * 32, tid);
        p_load(bbase + s * P_AST * 4, g_xcat + (size_t)n0 * 768, 768, s * 32, tid);
        asm volatile("cp.async.commit_group;" ::: "memory");
    }
    const int NI = 8;
#pragma unroll 1
    for (int i = 0; i < NI; i++) {
        int s = i & 1;
        if (i < NI - 1) asm volatile("cp.async.wait_group 1;" ::: "memory");
        else            asm volatile("cp.async.wait_group 0;" ::: "memory");
        __syncthreads();
        const uint32_t* As = sm2 + s * P_AST;
        const uint32_t* Bs = sm2 + 2 * P_AST + s * P_AST;
#pragma unroll
        for (int ks = 0; ks < 2; ks++) {
            uint32_t af[4][4];
#pragma unroll
            for (int mt = 0; mt < 4; mt++) {
                int b = (wm * 64 + mt * 16 + lq) * 20 + ks * 8 + lr;
                af[mt][0] = As[b]; af[mt][1] = As[b + 160];
                af[mt][2] = As[b + 4]; af[mt][3] = As[b + 164];
            }
            uint32_t bf[4][2];
#pragma unroll
            for (int nt = 0; nt < 4; nt++) {
                int b = (wn * 32 + nt * 8 + lq) * 20 + ks * 8 + lr;
                bf[nt][0] = Bs[b]; bf[nt][1] = Bs[b + 4];
            }
#pragma unroll
            for (int mt = 0; mt < 4; mt++)
#pragma unroll
                for (int nt = 0; nt < 4; nt++)
                    mma_f16(acc[mt][nt][0], acc[mt][nt][1], acc[mt][nt][2], acc[mt][nt][3],
                            af[mt][0], af[mt][1], af[mt][2], af[mt][3],
                            bf[nt][0], bf[nt][1]);
        }
        __syncthreads();
        if (i + 2 < NI) {
            p_load(abase + s * P_AST * 4, g_wp2h, 256, (i + 2) * 32, tid);
            p_load(bbase + s * P_AST * 4, g_xcat + (size_t)n0 * 768, 768, (i + 2) * 32, tid);
            asm volatile("cp.async.commit_group;" ::: "memory");
        }
    }
#pragma unroll
    for (int mt = 0; mt < 4; mt++)
#pragma unroll
        for (int nt = 0; nt < 4; nt++) {
            int r = wm * 64 + mt * 16 + lq;
            int n = n0 + wn * 32 + nt * 8 + lr * 2;
            __half2 v0; v0.x = __float2half_rn(acc[mt][nt][0]); v0.y = __float2half_rn(acc[mt][nt][1]);
            __half2 v1; v1.x = __float2half_rn(acc[mt][nt][2]); v1.y = __float2half_rn(acc[mt][nt][3]);
            *reinterpret_cast<__half2*>(g_yTh + (size_t)r * NROWS + n) = v0;
            *reinterpret_cast<__half2*>(g_yTh + (size_t)(r + 8) * NROWS + n) = v1;
        }
}

// ================= P3: xp = xcat @ wcat^T  (C [16384][128] fp32) =======
// grid 128 CTAs (128 rows each), 256 threads, 8 warps: 4M x 2N, warp 32x64.
__global__ __launch_bounds__(256)
void p3_xp() {
    extern __shared__ uint32_t sm3[];
    const int tid = threadIdx.x, wid = tid >> 5, lane = tid & 31;
    const int lq = lane >> 2, lr = lane & 3;
    const int wm = wid & 3, wn = wid >> 2;
    const int m0 = blockIdx.x * 128;
    uint32_t abase = cvta_smem(sm3);
    uint32_t bbase = abase + 2 * P_AST * 4;

    float acc[2][8][4];
#pragma unroll
    for (int i = 0; i < 2; i++)
#pragma unroll
        for (int j = 0; j < 8; j++)
#pragma unroll
            for (int v = 0; v < 4; v++) acc[i][j][v] = 0.f;

#pragma unroll
    for (int s = 0; s < 2; s++) {
        p_load(abase + s * P_AST * 4, g_xcat + (size_t)m0 * 768, 768, s * 32, tid);
        p_load(bbase + s * P_AST * 4, g_wcat, 768, s * 32, tid);
        asm volatile("cp.async.commit_group;" ::: "memory");
    }
    const int NI = 24;
#pragma unroll 1
    for (int i = 0; i < NI; i++) {
        int s = i & 1;
        if (i < NI - 1) asm volatile("cp.async.wait_group 1;" ::: "memory");
        else            asm volatile("cp.async.wait_group 0;" ::: "memory");
        __syncthreads();
        const uint32_t* As = sm3 + s * P_AST;
        const uint32_t* Bs = sm3 + 2 * P_AST + s * P_AST;
#pragma unroll
        for (int ks = 0; ks < 2; ks++) {
            uint32_t af[2][4];
#pragma unroll
            for (int mt = 0; mt < 2; mt++) {
                int b = (wm * 32 + mt * 16 + lq) * 20 + ks * 8 + lr;
                af[mt][0] = As[b]; af[mt][1] = As[b + 160];
                af[mt][2] = As[b + 4]; af[mt][3] = As[b + 164];
            }
            uint32_t bf[8][2];
#pragma unroll
            for (int nt = 0; nt < 8; nt++) {
                int b = (wn * 64 + nt * 8 + lq) * 20 + ks * 8 + lr;
                bf[nt][0] = Bs[b]; bf[nt][1] = Bs[b + 4];
            }
#pragma unroll
            for (int mt = 0; mt < 2; mt++)
#pragma unroll
                for (int nt = 0; nt < 8; nt++)
                    mma_f16(acc[mt][nt][0], acc[mt][nt][1], acc[mt][nt][2], acc[mt][nt][3],
                            af[mt][0], af[mt][1], af[mt][2], af[mt][3],
                            bf[nt][0], bf[nt][1]);
        }
        __syncthreads();
        if (i + 2 < NI) {
            p_load(abase + s * P_AST * 4, g_xcat + (size_t)m0 * 768, 768, (i + 2) * 32, tid);
            p_load(bbase + s * P_AST * 4, g_wcat, 768, (i + 2) * 32, tid);
            asm volatile("cp.async.commit_group;" ::: "memory");
        }
    }
#pragma unroll
    for (int mt = 0; mt < 2; mt++)
#pragma unroll
        for (int nt = 0; nt < 8; nt++) {
            int r = m0 + wm * 32 + mt * 16 + lq;
            int c = wn * 64 + nt * 8 + lr * 2;
            *reinterpret_cast<float2*>(g_xp + (size_t)r * 128 + c) =
                make_float2(acc[mt][nt][0], acc[mt][nt][1]);
            *reinterpret_cast<float2*>(g_xp + (size_t)(r + 8) * 128 + c) =
                make_float2(acc[mt][nt][2], acc[mt][nt][3]);
        }
}

// ================= Kernel Z: z = adj @ y, fused h/MLP/softmax epilogue ====
#define ZA_ST 2560            // 128 rows * 20 u32 (fp16 A stage)
#define ZB_ST 2560            // 128 n-rows * 20 u32
#define NIZ   512
// epilogue smem offsets (floats)
#define H_OFF   0             // 128 x 132
#define H1_OFF  16896         // 128 x 68
#define W1T_OFF 25600         // 128 x 64
#define H2_OFF  33792         // 128 x 36
#define W2T_OFF 38400         // 64 x 32
#define W3T_OFF 40448         // 32 x 8
#define LG_OFF  40704         // 128 x 8
#define DEG_OFF 41728         // 128
#define Z_SMEM_FLOATS 41856

__global__ __launch_bounds__(512, 1)
void gemm_z(const float* __restrict__ adj,
            const float* __restrict__ W1, const float* __restrict__ b1,
            const float* __restrict__ W2, const float* __restrict__ b2,
            const float* __restrict__ W3, const float* __restrict__ b3,
            float* __restrict__ out) {
    extern __shared__ uint32_t smz[];
    uint32_t* Abuf = smz;
    uint32_t* Bbuf = smz + 2 * ZA_ST;
    float* pool = reinterpret_cast<float*>(smz);

    const int tid = threadIdx.x, wid = tid >> 5, lane = tid & 31;
    const int lq = lane >> 2, lr = lane & 3;
    const int gg = lane >> 3, cc = lane & 7;
    const int wm = wid & 3, wn = wid >> 2;      // 4M x 4N warps, tile 32x32
    const int m0 = blockIdx.x * 128;
    const uint32_t bbase = cvta_smem(Bbuf);

    float acc[2][4][4];
#pragma unroll
    for (int i = 0; i < 2; i++)
#pragma unroll
        for (int j = 0; j < 4; j++)
#pragma unroll
            for (int v = 0; v < 4; v++) acc[i][j][v] = 0.f;

    // B prologue (3 stages)
#pragma unroll
    for (int s = 0; s < 3; s++) {
        int n = tid >> 2, c4 = tid & 3;
        cp16(bbase + s * (ZB_ST * 4) + n * 80 + c4 * 16,
             g_yTh + (size_t)n * NROWS + s * 32 + c4 * 8);
        asm volatile("cp.async.commit_group;" ::: "memory");
    }

    const int rowA0 = wid * 8 + gg;
    float4 areg[2];
#pragma unroll
    for (int p = 0; p < 2; p++)
        areg[p] = *reinterpret_cast<const float4*>(
            adj + (size_t)(m0 + rowA0 + p * 4) * NROWS + cc * 4);
    float degp[2] = {0.f, 0.f};

#pragma unroll 1
    for (int i = 0; i < NIZ; i++) {
        const int sA = i & 1;
        const int sB = i % 3;
#pragma unroll
        for (int p = 0; p < 2; p++) {
            float4 v = areg[p];
            degp[p] += (v.x + v.y) + (v.z + v.w);
            __half2 h0 = __floats2half2_rn(v.x, v.y);
            __half2 h1 = __floats2half2_rn(v.z, v.w);
            uint32_t* dst = Abuf + sA * ZA_ST + (rowA0 + p * 4) * 20 + cc * 2;
            dst[0] = h2u(h0);
            dst[1] = h2u(h1);
        }
        if (i + 1 < NIZ) {
            int k0n = (i + 1) * 32;
#pragma unroll
            for (int p = 0; p < 2; p++)
                areg[p] = *reinterpret_cast<const float4*>(
                    adj + (size_t)(m0 + rowA0 + p * 4) * NROWS + k0n + cc * 4);
        }
        int rem = (NIZ - 1) - i;
        if (rem >= 2)      asm volatile("cp.async.wait_group 2;" ::: "memory");
        else if (rem == 1) asm volatile("cp.async.wait_group 1;" ::: "memory");
        else               asm volatile("cp.async.wait_group 0;" ::: "memory");
        __syncthreads();

        const uint32_t* As = Abuf + sA * ZA_ST;
        const uint32_t* Bs = Bbuf + sB * ZB_ST;
#pragma unroll
        for (int ks = 0; ks < 2; ks++) {
            uint32_t af[2][4];
#pragma unroll
            for (int mt = 0; mt < 2; mt++) {
                int b = (wm * 32 + mt * 16 + lq) * 20 + ks * 8 + lr;
                af[mt][0] = As[b]; af[mt][1] = As[b + 160];
                af[mt][2] = As[b + 4]; af[mt][3] = As[b + 164];
            }
            uint32_t bf[4][2];
#pragma unroll
            for (int nt = 0; nt < 4; nt++) {
                int b = (wn * 32 + nt * 8 + lq) * 20 + ks * 8 + lr;
                bf[nt][0] = Bs[b]; bf[nt][1] = Bs[b + 4];
            }
#pragma unroll
            for (int mt = 0; mt < 2; mt++)
#pragma unroll
                for (int nt = 0; nt < 4; nt++)
                    mma_f16(acc[mt][nt][0], acc[mt][nt][1], acc[mt][nt][2], acc[mt][nt][3],
                            af[mt][0], af[mt][1], af[mt][2], af[mt][3],
                            bf[nt][0], bf[nt][1]);
        }
        __syncthreads();
        if (i + 3 < NIZ) {
            int sN = (i + 3) % 3;
            int n = tid >> 2, c4 = tid & 3;
            cp16(bbase + sN * (ZB_ST * 4) + n * 80 + c4 * 16,
                 g_yTh + (size_t)n * NROWS + (i + 3) * 32 + c4 * 8);
            asm volatile("cp.async.commit_group;" ::: "memory");
        }
    }

    // ---- deg to smem ----
#pragma unroll
    for (int p = 0; p < 2; p++) {
        float d = degp[p];
#pragma unroll
        for (int off = 1; off < 8; off <<= 1)
            d += __shfl_xor_sync(0xffffffffu, d, off);
        if (cc == 0) pool[DEG_OFF + rowA0 + p * 4] = d + 1.0f;
    }
    __syncthreads();

    // ---- h = relu(xp + z/deg) -> smem ----
#pragma unroll
    for (int mt = 0; mt < 2; mt++) {
        int r = wm * 32 + mt * 16 + lq;
        float inv0 = 1.0f / pool[DEG_OFF + r];
        float inv1 = 1.0f / pool[DEG_OFF + r + 8];
#pragma unroll
        for (int nt = 0; nt < 4; nt++) {
            int c = wn * 32 + nt * 8 + lr * 2;
            float2 x0 = *reinterpret_cast<const float2*>(g_xp + (size_t)(m0 + r) * 128 + c);
            float2 x1 = *reinterpret_cast<const float2*>(g_xp + (size_t)(m0 + r + 8) * 128 + c);
            pool[H_OFF + r * 132 + c]           = fmaxf(x0.x + acc[mt][nt][0] * inv0, 0.f);
            pool[H_OFF + r * 132 + c + 1]       = fmaxf(x0.y + acc[mt][nt][1] * inv0, 0.f);
            pool[H_OFF + (r + 8) * 132 + c]     = fmaxf(x1.x + acc[mt][nt][2] * inv1, 0.f);
            pool[H_OFF + (r + 8) * 132 + c + 1] = fmaxf(x1.y + acc[mt][nt][3] * inv1, 0.f);
        }
    }
    // stage W1T/W2T/W3T
    for (int idx = tid; idx < 8192; idx += 512) {
        int j = idx >> 7, k = idx & 127;
        pool[W1T_OFF + k * 64 + j] = W1[idx];
    }
    for (int idx = tid; idx < 2048; idx += 512) {
        int j = idx >> 6, k = idx & 63;
        pool[W2T_OFF + k * 32 + j] = W2[idx];
    }
    if (tid < 256) {
        int j = tid >> 5, k = tid & 31;
        pool[W3T_OFF + k * 8 + j] = W3[tid];
    }
    __syncthreads();

    // ---- MLP1: h1 = lrelu(h @ W1^T + b1)  (128x64) ----
    {
        const int jg = tid & 15, rg = tid >> 4;    // 4 j x 4 r per thread
        float a[4][4];
#pragma unroll
        for (int jj = 0; jj < 4; jj++) {
            float bb = b1[jg * 4 + jj];
#pragma unroll
            for (int ri = 0; ri < 4; ri++) a[ri][jj] = bb;
        }
#pragma unroll 4
        for (int k = 0; k < 128; k++) {
            float4 wv = *reinterpret_cast<const float4*>(&pool[W1T_OFF + k * 64 + jg * 4]);
#pragma unroll
            for (int ri = 0; ri < 4; ri++) {
                float hv = pool[H_OFF + (rg * 4 + ri) * 132 + k];
                a[ri][0] += hv * wv.x; a[ri][1] += hv * wv.y;
                a[ri][2] += hv * wv.z; a[ri][3] += hv * wv.w;
            }
        }
#pragma unroll
        for (int ri = 0; ri < 4; ri++)
#pragma unroll
            for (int jj = 0; jj < 4; jj++) {
                float v = a[ri][jj];
                pool[H1_OFF + (rg * 4 + ri) * 68 + jg * 4 + jj] = (v > 0.f) ? v : 0.01f * v;
            }
    }
    __syncthreads();

    // ---- MLP2: h2 = lrelu(h1 @ W2^T + b2) (128x32) ----
#pragma unroll
    for (int ii = 0; ii < 8; ii++) {
        int o = tid + 512 * ii;
        int r = o >> 5, j = o & 31;
        float a = b2[j];
#pragma unroll 8
        for (int k = 0; k < 64; k++)
            a += pool[H1_OFF + r * 68 + k] * pool[W2T_OFF + k * 32 + j];
        pool[H2_OFF + r * 36 + j] = (a > 0.f) ? a : 0.01f * a;
    }
    __syncthreads();

    // ---- MLP3: logits (128x8) ----
#pragma unroll
    for (int ii = 0; ii < 2; ii++) {
        int o = tid + 512 * ii;
        int r = o >> 3, j = o & 7;
        float a = b3[j];
#pragma unroll
        for (int k = 0; k < 32; k++)
            a += pool[H2_OFF + r * 36 + k] * pool[W3T_OFF + k * 8 + j];
        pool[LG_OFF + r * 8 + j] = (a > 0.f) ? a : 0.01f * a;
    }
    __syncthreads();

    // ---- softmax + write ----
    if (tid < 128) {
        int r = tid;
        float vv[8], m = -1e30f;
#pragma unroll
        for (int c = 0; c < 8; c++) {
            vv[c] = pool[LG_OFF + r * 8 + c];
            m = fmaxf(m, vv[c]);
        }
        float s = 0.f;
#pragma unroll
        for (int c = 0; c < 8; c++) { vv[c] = expf(vv[c] - m); s += vv[c]; }
        float inv = 1.0f / s;
        float4 o0 = make_float4(vv[0] * inv, vv[1] * inv, vv[2] * inv, vv[3] * inv);
        float4 o1 = make_float4(vv[4] * inv, vv[5] * inv, vv[6] * inv, vv[7] * inv);
        *reinterpret_cast<float4*>(out + (size_t)(m0 + r) * 8)     = o0;
        *reinterpret_cast<float4*>(out + (size_t)(m0 + r) * 8 + 4) = o1;
    }
}

// ---------------- launch ----------------
extern "C" void kernel_launch(void* const* d_in, const int* in_sizes, int n_in,
                              void* d_out, int out_size) {
    const float* x   = (const float*)d_in[0];
    const float* adj = (const float*)d_in[1];
    const float* Wp  = (const float*)d_in[2];
    const float* W1  = (const float*)d_in[3];
    const float* b1  = (const float*)d_in[4];
    const float* W2  = (const float*)d_in[5];
    const float* b2  = (const float*)d_in[6];
    const float* W3  = (const float*)d_in[7];
    const float* b3  = (const float*)d_in[8];
    float* out = (float*)d_out;

    const int psm = 4 * P_AST * 4;                  // 40960
    const int zsm = Z_SMEM_FLOATS * 4;              // 167424
    cudaFuncSetAttribute(p2_yT, cudaFuncAttributeMaxDynamicSharedMemorySize, psm);
    cudaFuncSetAttribute(p3_xp, cudaFuncAttributeMaxDynamicSharedMemorySize, psm);
    cudaFuncSetAttribute(gemm_z, cudaFuncAttributeMaxDynamicSharedMemorySize, zsm);

    convert_x<<<4096, 256>>>(x);
    convert_w<<<256, 256>>>(Wp);
    p2_yT<<<128, 256, psm>>>();
    p3_xp<<<128, 256, psm>>>();
    gemm_z<<<128, 512, zsm>>>(adj, W1, b1, W2, b2, W3, b3, out);
}

// round 11
// speedup vs baseline: 1.3813x; 1.0007x over previous
#include <cuda_runtime.h>
#include <cuda_fp16.h>
#include <cstdint>

#define NROWS 16384
#define NF    256

// ---------------- scratch (no allocations allowed) ----------------
__device__ __half g_xcat[NROWS * 768];     // [x_hi | x_hi | x_lo] per row
__device__ __half g_wcat[128 * 768];       // [w1_hi | w1_lo | w1_hi] per out
__device__ __half g_wp2h[128 * 256];       // Wp[:,256:512] fp16
__device__ __half g_yTh[128 * NROWS];      // yT = Wp2h @ x^T  [128][16384]
__device__ float  g_xp[NROWS * 128];       // x @ Wp1^T (split-fp16 accurate)

// ---------------- helpers ----------------
__device__ __forceinline__ void cp16(uint32_t saddr, const void* gaddr) {
    asm volatile("cp.async.cg.shared.global [%0], [%1], 16;"
                 :: "r"(saddr), "l"(gaddr));
}
__device__ __forceinline__ uint32_t cvta_smem(const void* p) {
    uint32_t a;
    asm("{ .reg .u64 t; cvta.to.shared.u64 t, %1; cvt.u32.u64 %0, t; }"
        : "=r"(a) : "l"(p));
    return a;
}
__device__ __forceinline__ void mma_f16(float& d0, float& d1, float& d2, float& d3,
                                        uint32_t a0, uint32_t a1, uint32_t a2, uint32_t a3,
                                        uint32_t b0, uint32_t b1) {
    asm volatile(
        "mma.sync.aligned.m16n8k16.row.col.f32.f16.f16.f32 "
        "{%0,%1,%2,%3}, {%4,%5,%6,%7}, {%8,%9}, {%0,%1,%2,%3};"
        : "+f"(d0), "+f"(d1), "+f"(d2), "+f"(d3)
        : "r"(a0), "r"(a1), "r"(a2), "r"(a3), "r"(b0), "r"(b1));
}
__device__ __forceinline__ uint32_t h2u(__half2 h) {
    return *reinterpret_cast<uint32_t*>(&h);
}

// ================= P1: conversions =================
__global__ __launch_bounds__(256)
void convert_x(const float* __restrict__ x) {
    int idx = blockIdx.x * 256 + threadIdx.x;   // 1,048,576 total
    int row = idx >> 6;
    int c   = (idx & 63) * 4;
    float4 v = *reinterpret_cast<const float4*>(x + (size_t)row * NF + c);
    __half hx = __float2half_rn(v.x), hy = __float2half_rn(v.y);
    __half hz = __float2half_rn(v.z), hw = __float2half_rn(v.w);
    __half lx = __float2half_rn(v.x - __half2float(hx));
    __half ly = __float2half_rn(v.y - __half2float(hy));
    __half lz = __float2half_rn(v.z - __half2float(hz));
    __half lw = __float2half_rn(v.w - __half2float(hw));
    __half2* base = reinterpret_cast<__half2*>(g_xcat + (size_t)row * 768);
    __half2 h01; h01.x = hx; h01.y = hy;
    __half2 h23; h23.x = hz; h23.y = hw;
    __half2 l01; l01.x = lx; l01.y = ly;
    __half2 l23; l23.x = lz; l23.y = lw;
    base[c / 2]             = h01;  base[c / 2 + 1]             = h23;
    base[(256 + c) / 2]     = h01;  base[(256 + c) / 2 + 1]     = h23;
    base[(512 + c) / 2]     = l01;  base[(512 + c) / 2 + 1]     = l23;
}

__global__ __launch_bounds__(256)
void convert_w(const float* __restrict__ Wp) {
    int idx = blockIdx.x * 256 + threadIdx.x;   // 65536 total
    int n = idx >> 9, c = idx & 511;
    float v = Wp[idx];
    __half h = __float2half_rn(v);
    if (c < 256) {
        __half l = __float2half_rn(v - __half2float(h));
        g_wcat[n * 768 + c]       = h;
        g_wcat[n * 768 + 256 + c] = l;
        g_wcat[n * 768 + 512 + c] = h;
    } else {
        g_wp2h[n * 256 + (c - 256)] = h;
    }
}

// ================= P2: yT = Wp2h @ x^T  (C [128][16384] fp16) =========
// grid 128 CTAs (128 node-cols each), 256 threads, 8 warps: 2M x 4N, warp 64x32.
#define P_AST 2560           // 128 rows * 20 u32
__device__ __forceinline__ void p_load(uint32_t dst, const __half* src,
                                       int pitch, int k0, int tid) {
#pragma unroll
    for (int j = 0; j < 2; j++) {
        int q = tid + 256 * j;
        int r = q >> 2, cc = q & 3;
        cp16(dst + r * 80 + cc * 16, src + (size_t)r * pitch + k0 + cc * 8);
    }
}

__global__ __launch_bounds__(256)
void p2_yT() {
    extern __shared__ uint32_t sm2[];
    const int tid = threadIdx.x, wid = tid >> 5, lane = tid & 31;
    const int lq = lane >> 2, lr = lane & 3;
    const int wm = wid & 1, wn = wid >> 1;
    const int n0 = blockIdx.x * 128;
    uint32_t abase = cvta_smem(sm2);
    uint32_t bbase = abase + 2 * P_AST * 4;

    float acc[4][4][4];
#pragma unroll
    for (int i = 0; i < 4; i++)
#pragma unroll
        for (int j = 0; j < 4; j++)
#pragma unroll
            for (int v = 0; v < 4; v++) acc[i][j][v] = 0.f;

#pragma unroll
    for (int s = 0; s < 2; s++) {
        p_load(abase + s * P_AST * 4, g_wp2h, 256, s * 32, tid);
        p_load(bbase + s * P_AST * 4, g_xcat + (size_t)n0 * 768, 768, s * 32, tid);
        asm volatile("cp.async.commit_group;" ::: "memory");
    }
    const int NI = 8;
#pragma unroll 1
    for (int i = 0; i < NI; i++) {
        int s = i & 1;
        if (i < NI - 1) asm volatile("cp.async.wait_group 1;" ::: "memory");
        else            asm volatile("cp.async.wait_group 0;" ::: "memory");
        __syncthreads();
        const uint32_t* As = sm2 + s * P_AST;
        const uint32_t* Bs = sm2 + 2 * P_AST + s * P_AST;
#pragma unroll
        for (int ks = 0; ks < 2; ks++) {
            uint32_t af[4][4];
#pragma unroll
            for (int mt = 0; mt < 4; mt++) {
                int b = (wm * 64 + mt * 16 + lq) * 20 + ks * 8 + lr;
                af[mt][0] = As[b]; af[mt][1] = As[b + 160];
                af[mt][2] = As[b + 4]; af[mt][3] = As[b + 164];
            }
            uint32_t bf[4][2];
#pragma unroll
            for (int nt = 0; nt < 4; nt++) {
                int b = (wn * 32 + nt * 8 + lq) * 20 + ks * 8 + lr;
                bf[nt][0] = Bs[b]; bf[nt][1] = Bs[b + 4];
            }
#pragma unroll
            for (int mt = 0; mt < 4; mt++)
#pragma unroll
                for (int nt = 0; nt < 4; nt++)
                    mma_f16(acc[mt][nt][0], acc[mt][nt][1], acc[mt][nt][2], acc[mt][nt][3],
                            af[mt][0], af[mt][1], af[mt][2], af[mt][3],
                            bf[nt][0], bf[nt][1]);
        }
        __syncthreads();
        if (i + 2 < NI) {
            p_load(abase + s * P_AST * 4, g_wp2h, 256, (i + 2) * 32, tid);
            p_load(bbase + s * P_AST * 4, g_xcat + (size_t)n0 * 768, 768, (i + 2) * 32, tid);
            asm volatile("cp.async.commit_group;" ::: "memory");
        }
    }
#pragma unroll
    for (int mt = 0; mt < 4; mt++)
#pragma unroll
        for (int nt = 0; nt < 4; nt++) {
            int r = wm * 64 + mt * 16 + lq;
            int n = n0 + wn * 32 + nt * 8 + lr * 2;
            __half2 v0; v0.x = __float2half_rn(acc[mt][nt][0]); v0.y = __float2half_rn(acc[mt][nt][1]);
            __half2 v1; v1.x = __float2half_rn(acc[mt][nt][2]); v1.y = __float2half_rn(acc[mt][nt][3]);
            *reinterpret_cast<__half2*>(g_yTh + (size_t)r * NROWS + n) = v0;
            *reinterpret_cast<__half2*>(g_yTh + (size_t)(r + 8) * NROWS + n) = v1;
        }
}

// ================= P3: xp = xcat @ wcat^T  (C [16384][128] fp32) =======
// grid 128 CTAs (128 rows each), 256 threads, 8 warps: 4M x 2N, warp 32x64.
__global__ __launch_bounds__(256)
void p3_xp() {
    extern __shared__ uint32_t sm3[];
    const int tid = threadIdx.x, wid = tid >> 5, lane = tid & 31;
    const int lq = lane >> 2, lr = lane & 3;
    const int wm = wid & 3, wn = wid >> 2;
    const int m0 = blockIdx.x * 128;
    uint32_t abase = cvta_smem(sm3);
    uint32_t bbase = abase + 2 * P_AST * 4;

    float acc[2][8][4];
#pragma unroll
    for (int i = 0; i < 2; i++)
#pragma unroll
        for (int j = 0; j < 8; j++)
#pragma unroll
            for (int v = 0; v < 4; v++) acc[i][j][v] = 0.f;

#pragma unroll
    for (int s = 0; s < 2; s++) {
        p_load(abase + s * P_AST * 4, g_xcat + (size_t)m0 * 768, 768, s * 32, tid);
        p_load(bbase + s * P_AST * 4, g_wcat, 768, s * 32, tid);
        asm volatile("cp.async.commit_group;" ::: "memory");
    }
    const int NI = 24;
#pragma unroll 1
    for (int i = 0; i < NI; i++) {
        int s = i & 1;
        if (i < NI - 1) asm volatile("cp.async.wait_group 1;" ::: "memory");
        else            asm volatile("cp.async.wait_group 0;" ::: "memory");
        __syncthreads();
        const uint32_t* As = sm3 + s * P_AST;
        const uint32_t* Bs = sm3 + 2 * P_AST + s * P_AST;
#pragma unroll
        for (int ks = 0; ks < 2; ks++) {
            uint32_t af[2][4];
#pragma unroll
            for (int mt = 0; mt < 2; mt++) {
                int b = (wm * 32 + mt * 16 + lq) * 20 + ks * 8 + lr;
                af[mt][0] = As[b]; af[mt][1] = As[b + 160];
                af[mt][2] = As[b + 4]; af[mt][3] = As[b + 164];
            }
            uint32_t bf[8][2];
#pragma unroll
            for (int nt = 0; nt < 8; nt++) {
                int b = (wn * 64 + nt * 8 + lq) * 20 + ks * 8 + lr;
                bf[nt][0] = Bs[b]; bf[nt][1] = Bs[b + 4];
            }
#pragma unroll
            for (int mt = 0; mt < 2; mt++)
#pragma unroll
                for (int nt = 0; nt < 8; nt++)
                    mma_f16(acc[mt][nt][0], acc[mt][nt][1], acc[mt][nt][2], acc[mt][nt][3],
                            af[mt][0], af[mt][1], af[mt][2], af[mt][3],
                            bf[nt][0], bf[nt][1]);
        }
        __syncthreads();
        if (i + 2 < NI) {
            p_load(abase + s * P_AST * 4, g_xcat + (size_t)m0 * 768, 768, (i + 2) * 32, tid);
            p_load(bbase + s * P_AST * 4, g_wcat, 768, (i + 2) * 32, tid);
            asm volatile("cp.async.commit_group;" ::: "memory");
        }
    }
#pragma unroll
    for (int mt = 0; mt < 2; mt++)
#pragma unroll
        for (int nt = 0; nt < 8; nt++) {
            int r = m0 + wm * 32 + mt * 16 + lq;
            int c = wn * 64 + nt * 8 + lr * 2;
            *reinterpret_cast<float2*>(g_xp + (size_t)r * 128 + c) =
                make_float2(acc[mt][nt][0], acc[mt][nt][1]);
            *reinterpret_cast<float2*>(g_xp + (size_t)(r + 8) * 128 + c) =
                make_float2(acc[mt][nt][2], acc[mt][nt][3]);
        }
}

// ================= Kernel Z: z = adj @ y, fused h/MLP/softmax epilogue ====
#define ZA_ST 2560            // 128 rows * 20 u32 (fp16 A stage)
#define ZB_ST 2560            // 128 n-rows * 20 u32
#define NIZ   512
// epilogue smem offsets (floats)
#define H_OFF   0             // 128 x 132
#define H1_OFF  16896         // 128 x 68
#define W1T_OFF 25600         // 128 x 64
#define H2_OFF  33792         // 128 x 36
#define W2T_OFF 38400         // 64 x 32
#define W3T_OFF 40448         // 32 x 8
#define LG_OFF  40704         // 128 x 8
#define DEG_OFF 41728         // 128
#define Z_SMEM_FLOATS 41856

__global__ __launch_bounds__(512, 1)
void gemm_z(const float* __restrict__ adj,
            const float* __restrict__ W1, const float* __restrict__ b1,
            const float* __restrict__ W2, const float* __restrict__ b2,
            const float* __restrict__ W3, const float* __restrict__ b3,
            float* __restrict__ out) {
    extern __shared__ uint32_t smz[];
    uint32_t* Abuf = smz;
    uint32_t* Bbuf = smz + 2 * ZA_ST;
    float* pool = reinterpret_cast<float*>(smz);

    const int tid = threadIdx.x, wid = tid >> 5, lane = tid & 31;
    const int lq = lane >> 2, lr = lane & 3;
    const int gg = lane >> 3, cc = lane & 7;
    const int wm = wid & 3, wn = wid >> 2;      // 4M x 4N warps, tile 32x32
    const int m0 = blockIdx.x * 128;
    const uint32_t bbase = cvta_smem(Bbuf);

    float acc[2][4][4];
#pragma unroll
    for (int i = 0; i < 2; i++)
#pragma unroll
        for (int j = 0; j < 4; j++)
#pragma unroll
            for (int v = 0; v < 4; v++) acc[i][j][v] = 0.f;

    // B prologue (3 stages)
#pragma unroll
    for (int s = 0; s < 3; s++) {
        int n = tid >> 2, c4 = tid & 3;
        cp16(bbase + s * (ZB_ST * 4) + n * 80 + c4 * 16,
             g_yTh + (size_t)n * NROWS + s * 32 + c4 * 8);
        asm volatile("cp.async.commit_group;" ::: "memory");
    }

    const int rowA0 = wid * 8 + gg;
    float4 areg[2];
#pragma unroll
    for (int p = 0; p < 2; p++)
        areg[p] = *reinterpret_cast<const float4*>(
            adj + (size_t)(m0 + rowA0 + p * 4) * NROWS + cc * 4);
    float degp[2] = {0.f, 0.f};

#pragma unroll 1
    for (int i = 0; i < NIZ; i++) {
        const int sA = i & 1;
        const int sB = i % 3;
#pragma unroll
        for (int p = 0; p < 2; p++) {
            float4 v = areg[p];
            degp[p] += (v.x + v.y) + (v.z + v.w);
            __half2 h0 = __floats2half2_rn(v.x, v.y);
            __half2 h1 = __floats2half2_rn(v.z, v.w);
            uint32_t* dst = Abuf + sA * ZA_ST + (rowA0 + p * 4) * 20 + cc * 2;
            dst[0] = h2u(h0);
            dst[1] = h2u(h1);
        }
        if (i + 1 < NIZ) {
            int k0n = (i + 1) * 32;
#pragma unroll
            for (int p = 0; p < 2; p++)
                areg[p] = *reinterpret_cast<const float4*>(
                    adj + (size_t)(m0 + rowA0 + p * 4) * NROWS + k0n + cc * 4);
        }
        int rem = (NIZ - 1) - i;
        if (rem >= 2)      asm volatile("cp.async.wait_group 2;" ::: "memory");
        else if (rem == 1) asm volatile("cp.async.wait_group 1;" ::: "memory");
        else               asm volatile("cp.async.wait_group 0;" ::: "memory");
        __syncthreads();

        const uint32_t* As = Abuf + sA * ZA_ST;
        const uint32_t* Bs = Bbuf + sB * ZB_ST;
#pragma unroll
        for (int ks = 0; ks < 2; ks++) {
            uint32_t af[2][4];
#pragma unroll
            for (int mt = 0; mt < 2; mt++) {
                int b = (wm * 32 + mt * 16 + lq) * 20 + ks * 8 + lr;
                af[mt][0] = As[b]; af[mt][1] = As[b + 160];
                af[mt][2] = As[b + 4]; af[mt][3] = As[b + 164];
            }
            uint32_t bf[4][2];
#pragma unroll
            for (int nt = 0; nt < 4; nt++) {
                int b = (wn * 32 + nt * 8 + lq) * 20 + ks * 8 + lr;
                bf[nt][0] = Bs[b]; bf[nt][1] = Bs[b + 4];
            }
#pragma unroll
            for (int mt = 0; mt < 2; mt++)
#pragma unroll
                for (int nt = 0; nt < 4; nt++)
                    mma_f16(acc[mt][nt][0], acc[mt][nt][1], acc[mt][nt][2], acc[mt][nt][3],
                            af[mt][0], af[mt][1], af[mt][2], af[mt][3],
                            bf[nt][0], bf[nt][1]);
        }
        __syncthreads();
        if (i + 3 < NIZ) {
            int sN = (i + 3) % 3;
            int n = tid >> 2, c4 = tid & 3;
            cp16(bbase + sN * (ZB_ST * 4) + n * 80 + c4 * 16,
                 g_yTh + (size_t)n * NROWS + (i + 3) * 32 + c4 * 8);
            asm volatile("cp.async.commit_group;" ::: "memory");
        }
    }

    // ---- deg to smem ----
#pragma unroll
    for (int p = 0; p < 2; p++) {
        float d = degp[p];
#pragma unroll
        for (int off = 1; off < 8; off <<= 1)
            d += __shfl_xor_sync(0xffffffffu, d, off);
        if (cc == 0) pool[DEG_OFF + rowA0 + p * 4] = d + 1.0f;
    }
    __syncthreads();

    // ---- h = relu(xp + z/deg) -> smem ----
#pragma unroll
    for (int mt = 0; mt < 2; mt++) {
        int r = wm * 32 + mt * 16 + lq;
        float inv0 = 1.0f / pool[DEG_OFF + r];
        float inv1 = 1.0f / pool[DEG_OFF + r + 8];
#pragma unroll
        for (int nt = 0; nt < 4; nt++) {
            int c = wn * 32 + nt * 8 + lr * 2;
            float2 x0 = *reinterpret_cast<const float2*>(g_xp + (size_t)(m0 + r) * 128 + c);
            float2 x1 = *reinterpret_cast<const float2*>(g_xp + (size_t)(m0 + r + 8) * 128 + c);
            pool[H_OFF + r * 132 + c]           = fmaxf(x0.x + acc[mt][nt][0] * inv0, 0.f);
            pool[H_OFF + r * 132 + c + 1]       = fmaxf(x0.y + acc[mt][nt][1] * inv0, 0.f);
            pool[H_OFF + (r + 8) * 132 + c]     = fmaxf(x1.x + acc[mt][nt][2] * inv1, 0.f);
            pool[H_OFF + (r + 8) * 132 + c + 1] = fmaxf(x1.y + acc[mt][nt][3] * inv1, 0.f);
        }
    }
    // stage W1T/W2T/W3T
    for (int idx = tid; idx < 8192; idx += 512) {
        int j = idx >> 7, k = idx & 127;
        pool[W1T_OFF + k * 64 + j] = W1[idx];
    }
    for (int idx = tid; idx < 2048; idx += 512) {
        int j = idx >> 6, k = idx & 63;
        pool[W2T_OFF + k * 32 + j] = W2[idx];
    }
    if (tid < 256) {
        int j = tid >> 5, k = tid & 31;
        pool[W3T_OFF + k * 8 + j] = W3[tid];
    }
    __syncthreads();

    // ---- MLP1: h1 = lrelu(h @ W1^T + b1)  (128x64) ----
    {
        const int jg = tid & 15, rg = tid >> 4;    // 4 j x 4 r per thread
        float a[4][4];
#pragma unroll
        for (int jj = 0; jj < 4; jj++) {
            float bb = b1[jg * 4 + jj];
#pragma unroll
            for (int ri = 0; ri < 4; ri++) a[ri][jj] = bb;
        }
#pragma unroll 4
        for (int k = 0; k < 128; k++) {
            float4 wv = *reinterpret_cast<const float4*>(&pool[W1T_OFF + k * 64 + jg * 4]);
#pragma unroll
            for (int ri = 0; ri < 4; ri++) {
                float hv = pool[H_OFF + (rg * 4 + ri) * 132 + k];
                a[ri][0] += hv * wv.x; a[ri][1] += hv * wv.y;
                a[ri][2] += hv * wv.z; a[ri][3] += hv * wv.w;
            }
        }
#pragma unroll
        for (int ri = 0; ri < 4; ri++)
#pragma unroll
            for (int jj = 0; jj < 4; jj++) {
                float v = a[ri][jj];
                pool[H1_OFF + (rg * 4 + ri) * 68 + jg * 4 + jj] = (v > 0.f) ? v : 0.01f * v;
            }
    }
    __syncthreads();

    // ---- MLP2: h2 = lrelu(h1 @ W2^T + b2) (128x32) ----
#pragma unroll
    for (int ii = 0; ii < 8; ii++) {
        int o = tid + 512 * ii;
        int r = o >> 5, j = o & 31;
        float a = b2[j];
#pragma unroll 8
        for (int k = 0; k < 64; k++)
            a += pool[H1_OFF + r * 68 + k] * pool[W2T_OFF + k * 32 + j];
        pool[H2_OFF + r * 36 + j] = (a > 0.f) ? a : 0.01f * a;
    }
    __syncthreads();

    // ---- MLP3: logits (128x8) ----
#pragma unroll
    for (int ii = 0; ii < 2; ii++) {
        int o = tid + 512 * ii;
        int r = o >> 3, j = o & 7;
        float a = b3[j];
#pragma unroll
        for (int k = 0; k < 32; k++)
            a += pool[H2_OFF + r * 36 + k] * pool[W3T_OFF + k * 8 + j];
        pool[LG_OFF + r * 8 + j] = (a > 0.f) ? a : 0.01f * a;
    }
    __syncthreads();

    // ---- softmax + write ----
    if (tid < 128) {
        int r = tid;
        float vv[8], m = -1e30f;
#pragma unroll
        for (int c = 0; c < 8; c++) {
            vv[c] = pool[LG_OFF + r * 8 + c];
            m = fmaxf(m, vv[c]);
        }
        float s = 0.f;
#pragma unroll
        for (int c = 0; c < 8; c++) { vv[c] = expf(vv[c] - m); s += vv[c]; }
        float inv = 1.0f / s;
        float4 o0 = make_float4(vv[0] * inv, vv[1] * inv, vv[2] * inv, vv[3] * inv);
        float4 o1 = make_float4(vv[4] * inv, vv[5] * inv, vv[6] * inv, vv[7] * inv);
        *reinterpret_cast<float4*>(out + (size_t)(m0 + r) * 8)     = o0;
        *reinterpret_cast<float4*>(out + (size_t)(m0 + r) * 8 + 4) = o1;
    }
}

// ---------------- launch ----------------
extern "C" void kernel_launch(void* const* d_in, const int* in_sizes, int n_in,
                              void* d_out, int out_size) {
    const float* x   = (const float*)d_in[0];
    const float* adj = (const float*)d_in[1];
    const float* Wp  = (const float*)d_in[2];
    const float* W1  = (const float*)d_in[3];
    const float* b1  = (const float*)d_in[4];
    const float* W2  = (const float*)d_in[5];
    const float* b2  = (const float*)d_in[6];
    const float* W3  = (const float*)d_in[7];
    const float* b3  = (const float*)d_in[8];
    float* out = (float*)d_out;

    const int psm = 4 * P_AST * 4;                  // 40960
    const int zsm = Z_SMEM_FLOATS * 4;              // 167424
    cudaFuncSetAttribute(p2_yT, cudaFuncAttributeMaxDynamicSharedMemorySize, psm);
    cudaFuncSetAttribute(p3_xp, cudaFuncAttributeMaxDynamicSharedMemorySize, psm);
    cudaFuncSetAttribute(gemm_z, cudaFuncAttributeMaxDynamicSharedMemorySize, zsm);

    convert_x<<<4096, 256>>>(x);
    convert_w<<<256, 256>>>(Wp);
    p2_yT<<<128, 256, psm>>>();
    p3_xp<<<128, 256, psm>>>();
    gemm_z<<<128, 512, zsm>>>(adj, W1, b1, W2, b2, W3, b3, out);
}

// round 12
// speedup vs baseline: 1.3940x; 1.0091x over previous
#include <cuda_runtime.h>
#include <cuda_fp16.h>
#include <cstdint>

#define NROWS 16384
#define NF    256

// ---------------- scratch (no allocations allowed) ----------------
__device__ __half g_xcat[NROWS * 768];     // [x_hi | x_hi | x_lo] per row
__device__ __half g_wcat[128 * 768];       // [w1_hi | w1_lo | w1_hi] per out
__device__ __half g_wp2h[128 * 256];       // Wp[:,256:512] fp16
__device__ __half g_yTh[128 * NROWS];      // yT = Wp2h @ x^T  [128][16384]
__device__ float  g_xp[NROWS * 128];       // x @ Wp1^T (split-fp16 accurate)

// ---------------- helpers ----------------
__device__ __forceinline__ void cp16(uint32_t saddr, const void* gaddr) {
    asm volatile("cp.async.cg.shared.global [%0], [%1], 16;"
                 :: "r"(saddr), "l"(gaddr));
}
__device__ __forceinline__ uint32_t cvta_smem(const void* p) {
    uint32_t a;
    asm("{ .reg .u64 t; cvta.to.shared.u64 t, %1; cvt.u32.u64 %0, t; }"
        : "=r"(a) : "l"(p));
    return a;
}
__device__ __forceinline__ void mma_f16(float& d0, float& d1, float& d2, float& d3,
                                        uint32_t a0, uint32_t a1, uint32_t a2, uint32_t a3,
                                        uint32_t b0, uint32_t b1) {
    asm volatile(
        "mma.sync.aligned.m16n8k16.row.col.f32.f16.f16.f32 "
        "{%0,%1,%2,%3}, {%4,%5,%6,%7}, {%8,%9}, {%0,%1,%2,%3};"
        : "+f"(d0), "+f"(d1), "+f"(d2), "+f"(d3)
        : "r"(a0), "r"(a1), "r"(a2), "r"(a3), "r"(b0), "r"(b1));
}
__device__ __forceinline__ uint32_t h2u(__half2 h) {
    return *reinterpret_cast<uint32_t*>(&h);
}

// ================= P1: conversions =================
__global__ __launch_bounds__(256)
void convert_x(const float* __restrict__ x) {
    int idx = blockIdx.x * 256 + threadIdx.x;   // 1,048,576 total
    int row = idx >> 6;
    int c   = (idx & 63) * 4;
    float4 v = *reinterpret_cast<const float4*>(x + (size_t)row * NF + c);
    __half hx = __float2half_rn(v.x), hy = __float2half_rn(v.y);
    __half hz = __float2half_rn(v.z), hw = __float2half_rn(v.w);
    __half lx = __float2half_rn(v.x - __half2float(hx));
    __half ly = __float2half_rn(v.y - __half2float(hy));
    __half lz = __float2half_rn(v.z - __half2float(hz));
    __half lw = __float2half_rn(v.w - __half2float(hw));
    __half2* base = reinterpret_cast<__half2*>(g_xcat + (size_t)row * 768);
    __half2 h01; h01.x = hx; h01.y = hy;
    __half2 h23; h23.x = hz; h23.y = hw;
    __half2 l01; l01.x = lx; l01.y = ly;
    __half2 l23; l23.x = lz; l23.y = lw;
    base[c / 2]             = h01;  base[c / 2 + 1]             = h23;
    base[(256 + c) / 2]     = h01;  base[(256 + c) / 2 + 1]     = h23;
    base[(512 + c) / 2]     = l01;  base[(512 + c) / 2 + 1]     = l23;
}

__global__ __launch_bounds__(256)
void convert_w(const float* __restrict__ Wp) {
    int idx = blockIdx.x * 256 + threadIdx.x;   // 65536 total
    int n = idx >> 9, c = idx & 511;
    float v = Wp[idx];
    __half h = __float2half_rn(v);
    if (c < 256) {
        __half l = __float2half_rn(v - __half2float(h));
        g_wcat[n * 768 + c]       = h;
        g_wcat[n * 768 + 256 + c] = l;
        g_wcat[n * 768 + 512 + c] = h;
    } else {
        g_wp2h[n * 256 + (c - 256)] = h;
    }
}

// ================= P2: yT = Wp2h @ x^T  (C [128][16384] fp16) =========
// grid 128 CTAs (128 node-cols each), 256 threads, 8 warps: 2M x 4N, warp 64x32.
#define P_AST 2560           // 128 rows * 20 u32
__device__ __forceinline__ void p_load(uint32_t dst, const __half* src,
                                       int pitch, int k0, int tid) {
#pragma unroll
    for (int j = 0; j < 2; j++) {
        int q = tid + 256 * j;
        int r = q >> 2, cc = q & 3;
        cp16(dst + r * 80 + cc * 16, src + (size_t)r * pitch + k0 + cc * 8);
    }
}

__global__ __launch_bounds__(256)
void p2_yT() {
    extern __shared__ uint32_t sm2[];
    const int tid = threadIdx.x, wid = tid >> 5, lane = tid & 31;
    const int lq = lane >> 2, lr = lane & 3;
    const int wm = wid & 1, wn = wid >> 1;
    const int n0 = blockIdx.x * 128;
    uint32_t abase = cvta_smem(sm2);
    uint32_t bbase = abase + 2 * P_AST * 4;

    float acc[4][4][4];
#pragma unroll
    for (int i = 0; i < 4; i++)
#pragma unroll
        for (int j = 0; j < 4; j++)
#pragma unroll
            for (int v = 0; v < 4; v++) acc[i][j][v] = 0.f;

#pragma unroll
    for (int s = 0; s < 2; s++) {
        p_load(abase + s * P_AST * 4, g_wp2h, 256, s * 32, tid);
        p_load(bbase + s * P_AST * 4, g_xcat + (size_t)n0 * 768, 768, s * 32, tid);
        asm volatile("cp.async.commit_group;" ::: "memory");
    }
    const int NI = 8;
#pragma unroll 1
    for (int i = 0; i < NI; i++) {
        int s = i & 1;
        if (i < NI - 1) asm volatile("cp.async.wait_group 1;" ::: "memory");
        else            asm volatile("cp.async.wait_group 0;" ::: "memory");
        __syncthreads();
        const uint32_t* As = sm2 + s * P_AST;
        const uint32_t* Bs = sm2 + 2 * P_AST + s * P_AST;
#pragma unroll
        for (int ks = 0; ks < 2; ks++) {
            uint32_t af[4][4];
#pragma unroll
            for (int mt = 0; mt < 4; mt++) {
                int b = (wm * 64 + mt * 16 + lq) * 20 + ks * 8 + lr;
                af[mt][0] = As[b]; af[mt][1] = As[b + 160];
                af[mt][2] = As[b + 4]; af[mt][3] = As[b + 164];
            }
            uint32_t bf[4][2];
#pragma unroll
            for (int nt = 0; nt < 4; nt++) {
                int b = (wn * 32 + nt * 8 + lq) * 20 + ks * 8 + lr;
                bf[nt][0] = Bs[b]; bf[nt][1] = Bs[b + 4];
            }
#pragma unroll
            for (int mt = 0; mt < 4; mt++)
#pragma unroll
                for (int nt = 0; nt < 4; nt++)
                    mma_f16(acc[mt][nt][0], acc[mt][nt][1], acc[mt][nt][2], acc[mt][nt][3],
                            af[mt][0], af[mt][1], af[mt][2], af[mt][3],
                            bf[nt][0], bf[nt][1]);
        }
        __syncthreads();
        if (i + 2 < NI) {
            p_load(abase + s * P_AST * 4, g_wp2h, 256, (i + 2) * 32, tid);
            p_load(bbase + s * P_AST * 4, g_xcat + (size_t)n0 * 768, 768, (i + 2) * 32, tid);
            asm volatile("cp.async.commit_group;" ::: "memory");
        }
    }
#pragma unroll
    for (int mt = 0; mt < 4; mt++)
#pragma unroll
        for (int nt = 0; nt < 4; nt++) {
            int r = wm * 64 + mt * 16 + lq;
            int n = n0 + wn * 32 + nt * 8 + lr * 2;
            __half2 v0; v0.x = __float2half_rn(acc[mt][nt][0]); v0.y = __float2half_rn(acc[mt][nt][1]);
            __half2 v1; v1.x = __float2half_rn(acc[mt][nt][2]); v1.y = __float2half_rn(acc[mt][nt][3]);
            *reinterpret_cast<__half2*>(g_yTh + (size_t)r * NROWS + n) = v0;
            *reinterpret_cast<__half2*>(g_yTh + (size_t)(r + 8) * NROWS + n) = v1;
        }
}

// ================= P3: xp = xcat @ wcat^T  (C [16384][128] fp32) =======
// grid 128 CTAs (128 rows each), 256 threads, 8 warps: 4M x 2N, warp 32x64.
__global__ __launch_bounds__(256)
void p3_xp() {
    extern __shared__ uint32_t sm3[];
    const int tid = threadIdx.x, wid = tid >> 5, lane = tid & 31;
    const int lq = lane >> 2, lr = lane & 3;
    const int wm = wid & 3, wn = wid >> 2;
    const int m0 = blockIdx.x * 128;
    uint32_t abase = cvta_smem(sm3);
    uint32_t bbase = abase + 2 * P_AST * 4;

    float acc[2][8][4];
#pragma unroll
    for (int i = 0; i < 2; i++)
#pragma unroll
        for (int j = 0; j < 8; j++)
#pragma unroll
            for (int v = 0; v < 4; v++) acc[i][j][v] = 0.f;

#pragma unroll
    for (int s = 0; s < 2; s++) {
        p_load(abase + s * P_AST * 4, g_xcat + (size_t)m0 * 768, 768, s * 32, tid);
        p_load(bbase + s * P_AST * 4, g_wcat, 768, s * 32, tid);
        asm volatile("cp.async.commit_group;" ::: "memory");
    }
    const int NI = 24;
#pragma unroll 1
    for (int i = 0; i < NI; i++) {
        int s = i & 1;
        if (i < NI - 1) asm volatile("cp.async.wait_group 1;" ::: "memory");
        else            asm volatile("cp.async.wait_group 0;" ::: "memory");
        __syncthreads();
        const uint32_t* As = sm3 + s * P_AST;
        const uint32_t* Bs = sm3 + 2 * P_AST + s * P_AST;
#pragma unroll
        for (int ks = 0; ks < 2; ks++) {
            uint32_t af[2][4];
#pragma unroll
            for (int mt = 0; mt < 2; mt++) {
                int b = (wm * 32 + mt * 16 + lq) * 20 + ks * 8 + lr;
                af[mt][0] = As[b]; af[mt][1] = As[b + 160];
                af[mt][2] = As[b + 4]; af[mt][3] = As[b + 164];
            }
            uint32_t bf[8][2];
#pragma unroll
            for (int nt = 0; nt < 8; nt++) {
                int b = (wn * 64 + nt * 8 + lq) * 20 + ks * 8 + lr;
                bf[nt][0] = Bs[b]; bf[nt][1] = Bs[b + 4];
            }
#pragma unroll
            for (int mt = 0; mt < 2; mt++)
#pragma unroll
                for (int nt = 0; nt < 8; nt++)
                    mma_f16(acc[mt][nt][0], acc[mt][nt][1], acc[mt][nt][2], acc[mt][nt][3],
                            af[mt][0], af[mt][1], af[mt][2], af[mt][3],
                            bf[nt][0], bf[nt][1]);
        }
        __syncthreads();
        if (i + 2 < NI) {
            p_load(abase + s * P_AST * 4, g_xcat + (size_t)m0 * 768, 768, (i + 2) * 32, tid);
            p_load(bbase + s * P_AST * 4, g_wcat, 768, (i + 2) * 32, tid);
            asm volatile("cp.async.commit_group;" ::: "memory");
        }
    }
#pragma unroll
    for (int mt = 0; mt < 2; mt++)
#pragma unroll
        for (int nt = 0; nt < 8; nt++) {
            int r = m0 + wm * 32 + mt * 16 + lq;
            int c = wn * 64 + nt * 8 + lr * 2;
            *reinterpret_cast<float2*>(g_xp + (size_t)r * 128 + c) =
                make_float2(acc[mt][nt][0], acc[mt][nt][1]);
            *reinterpret_cast<float2*>(g_xp + (size_t)(r + 8) * 128 + c) =
                make_float2(acc[mt][nt][2], acc[mt][nt][3]);
        }
}

// ================= Kernel Z: z = adj @ y, fused h/MLP/softmax epilogue ====
#define ZA_ST 2560            // 128 rows * 20 u32 (fp16 A stage)
#define ZB_ST 2560            // 128 n-rows * 20 u32
#define NIZ   512
// epilogue smem offsets (floats)
#define H_OFF   0             // 128 x 132
#define H1_OFF  16896         // 128 x 68
#define W1T_OFF 25600         // 128 x 64
#define H2_OFF  33792         // 128 x 36
#define W2T_OFF 38400         // 64 x 32
#define W3T_OFF 40448         // 32 x 8
#define LG_OFF  40704         // 128 x 8
#define DEG_OFF 41728         // 128
#define Z_SMEM_FLOATS 41856

__global__ __launch_bounds__(512, 1)
void gemm_z(const float* __restrict__ adj,
            const float* __restrict__ W1, const float* __restrict__ b1,
            const float* __restrict__ W2, const float* __restrict__ b2,
            const float* __restrict__ W3, const float* __restrict__ b3,
            float* __restrict__ out) {
    extern __shared__ uint32_t smz[];
    uint32_t* Abuf = smz;
    uint32_t* Bbuf = smz + 2 * ZA_ST;
    float* pool = reinterpret_cast<float*>(smz);

    const int tid = threadIdx.x, wid = tid >> 5, lane = tid & 31;
    const int lq = lane >> 2, lr = lane & 3;
    const int gg = lane >> 3, cc = lane & 7;
    const int wm = wid & 3, wn = wid >> 2;      // 4M x 4N warps, tile 32x32
    const int m0 = blockIdx.x * 128;
    const uint32_t bbase = cvta_smem(Bbuf);

    float acc[2][4][4];
#pragma unroll
    for (int i = 0; i < 2; i++)
#pragma unroll
        for (int j = 0; j < 4; j++)
#pragma unroll
            for (int v = 0; v < 4; v++) acc[i][j][v] = 0.f;

    // B prologue (3 stages)
#pragma unroll
    for (int s = 0; s < 3; s++) {
        int n = tid >> 2, c4 = tid & 3;
        cp16(bbase + s * (ZB_ST * 4) + n * 80 + c4 * 16,
             g_yTh + (size_t)n * NROWS + s * 32 + c4 * 8);
        asm volatile("cp.async.commit_group;" ::: "memory");
    }

    const int rowA0 = wid * 8 + gg;
    float4 areg[2];
#pragma unroll
    for (int p = 0; p < 2; p++)
        areg[p] = *reinterpret_cast<const float4*>(
            adj + (size_t)(m0 + rowA0 + p * 4) * NROWS + cc * 4);
    float degp[2] = {0.f, 0.f};

#pragma unroll 1
    for (int i = 0; i < NIZ; i++) {
        const int sA = i & 1;
        const int sB = i % 3;
#pragma unroll
        for (int p = 0; p < 2; p++) {
            float4 v = areg[p];
            degp[p] += (v.x + v.y) + (v.z + v.w);
            __half2 h0 = __floats2half2_rn(v.x, v.y);
            __half2 h1 = __floats2half2_rn(v.z, v.w);
            uint32_t* dst = Abuf + sA * ZA_ST + (rowA0 + p * 4) * 20 + cc * 2;
            dst[0] = h2u(h0);
            dst[1] = h2u(h1);
        }
        if (i + 1 < NIZ) {
            int k0n = (i + 1) * 32;
#pragma unroll
            for (int p = 0; p < 2; p++)
                areg[p] = *reinterpret_cast<const float4*>(
                    adj + (size_t)(m0 + rowA0 + p * 4) * NROWS + k0n + cc * 4);
        }
        int rem = (NIZ - 1) - i;
        if (rem >= 2)      asm volatile("cp.async.wait_group 2;" ::: "memory");
        else if (rem == 1) asm volatile("cp.async.wait_group 1;" ::: "memory");
        else               asm volatile("cp.async.wait_group 0;" ::: "memory");
        __syncthreads();

        const uint32_t* As = Abuf + sA * ZA_ST;
        const uint32_t* Bs = Bbuf + sB * ZB_ST;
#pragma unroll
        for (int ks = 0; ks < 2; ks++) {
            uint32_t af[2][4];
#pragma unroll
            for (int mt = 0; mt < 2; mt++) {
                int b = (wm * 32 + mt * 16 + lq) * 20 + ks * 8 + lr;
                af[mt][0] = As[b]; af[mt][1] = As[b + 160];
                af[mt][2] = As[b + 4]; af[mt][3] = As[b + 164];
            }
            uint32_t bf[4][2];
#pragma unroll
            for (int nt = 0; nt < 4; nt++) {
                int b = (wn * 32 + nt * 8 + lq) * 20 + ks * 8 + lr;
                bf[nt][0] = Bs[b]; bf[nt][1] = Bs[b + 4];
            }
#pragma unroll
            for (int mt = 0; mt < 2; mt++)
#pragma unroll
                for (int nt = 0; nt < 4; nt++)
                    mma_f16(acc[mt][nt][0], acc[mt][nt][1], acc[mt][nt][2], acc[mt][nt][3],
                            af[mt][0], af[mt][1], af[mt][2], af[mt][3],
                            bf[nt][0], bf[nt][1]);
        }
        __syncthreads();
        if (i + 3 < NIZ) {
            int sN = (i + 3) % 3;
            int n = tid >> 2, c4 = tid & 3;
            cp16(bbase + sN * (ZB_ST * 4) + n * 80 + c4 * 16,
                 g_yTh + (size_t)n * NROWS + (i + 3) * 32 + c4 * 8);
            asm volatile("cp.async.commit_group;" ::: "memory");
        }
    }

    // ---- deg to smem ----
#pragma unroll
    for (int p = 0; p < 2; p++) {
        float d = degp[p];
#pragma unroll
        for (int off = 1; off < 8; off <<= 1)
            d += __shfl_xor_sync(0xffffffffu, d, off);
        if (cc == 0) pool[DEG_OFF + rowA0 + p * 4] = d + 1.0f;
    }
    __syncthreads();

    // ---- h = relu(xp + z/deg) -> smem ----
#pragma unroll
    for (int mt = 0; mt < 2; mt++) {
        int r = wm * 32 + mt * 16 + lq;
        float inv0 = 1.0f / pool[DEG_OFF + r];
        float inv1 = 1.0f / pool[DEG_OFF + r + 8];
#pragma unroll
        for (int nt = 0; nt < 4; nt++) {
            int c = wn * 32 + nt * 8 + lr * 2;
            float2 x0 = *reinterpret_cast<const float2*>(g_xp + (size_t)(m0 + r) * 128 + c);
            float2 x1 = *reinterpret_cast<const float2*>(g_xp + (size_t)(m0 + r + 8) * 128 + c);
            pool[H_OFF + r * 132 + c]           = fmaxf(x0.x + acc[mt][nt][0] * inv0, 0.f);
            pool[H_OFF + r * 132 + c + 1]       = fmaxf(x0.y + acc[mt][nt][1] * inv0, 0.f);
            pool[H_OFF + (r + 8) * 132 + c]     = fmaxf(x1.x + acc[mt][nt][2] * inv1, 0.f);
            pool[H_OFF + (r + 8) * 132 + c + 1] = fmaxf(x1.y + acc[mt][nt][3] * inv1, 0.f);
        }
    }
    // stage W1T/W2T/W3T
    for (int idx = tid; idx < 8192; idx += 512) {
        int j = idx >> 7, k = idx & 127;
        pool[W1T_OFF + k * 64 + j] = W1[idx];
    }
    for (int idx = tid; idx < 2048; idx += 512) {
        int j = idx >> 6, k = idx & 63;
        pool[W2T_OFF + k * 32 + j] = W2[idx];
    }
    if (tid < 256) {
        int j = tid >> 5, k = tid & 31;
        pool[W3T_OFF + k * 8 + j] = W3[tid];
    }
    __syncthreads();

    // ---- MLP1: h1 = lrelu(h @ W1^T + b1)  (128x64) ----
    {
        const int jg = tid & 15, rg = tid >> 4;    // 4 j x 4 r per thread
        float a[4][4];
#pragma unroll
        for (int jj = 0; jj < 4; jj++) {
            float bb = b1[jg * 4 + jj];
#pragma unroll
            for (int ri = 0; ri < 4; ri++) a[ri][jj] = bb;
        }
#pragma unroll 4
        for (int k = 0; k < 128; k++) {
            float4 wv = *reinterpret_cast<const float4*>(&pool[W1T_OFF + k * 64 + jg * 4]);
#pragma unroll
            for (int ri = 0; ri < 4; ri++) {
                float hv = pool[H_OFF + (rg * 4 + ri) * 132 + k];
                a[ri][0] += hv * wv.x; a[ri][1] += hv * wv.y;
                a[ri][2] += hv * wv.z; a[ri][3] += hv * wv.w;
            }
        }
#pragma unroll
        for (int ri = 0; ri < 4; ri++)
#pragma unroll
            for (int jj = 0; jj < 4; jj++) {
                float v = a[ri][jj];
                pool[H1_OFF + (rg * 4 + ri) * 68 + jg * 4 + jj] = (v > 0.f) ? v : 0.01f * v;
            }
    }
    __syncthreads();

    // ---- MLP2: h2 = lrelu(h1 @ W2^T + b2) (128x32) ----
#pragma unroll
    for (int ii = 0; ii < 8; ii++) {
        int o = tid + 512 * ii;
        int r = o >> 5, j = o & 31;
        float a = b2[j];
#pragma unroll 8
        for (int k = 0; k < 64; k++)
            a += pool[H1_OFF + r * 68 + k] * pool[W2T_OFF + k * 32 + j];
        pool[H2_OFF + r * 36 + j] = (a > 0.f) ? a : 0.01f * a;
    }
    __syncthreads();

    // ---- MLP3: logits (128x8) ----
#pragma unroll
    for (int ii = 0; ii < 2; ii++) {
        int o = tid + 512 * ii;
        int r = o >> 3, j = o & 7;
        float a = b3[j];
#pragma unroll
        for (int k = 0; k < 32; k++)
            a += pool[H2_OFF + r * 36 + k] * pool[W3T_OFF + k * 8 + j];
        pool[LG_OFF + r * 8 + j] = (a > 0.f) ? a : 0.01f * a;
    }
    __syncthreads();

    // ---- softmax + write ----
    if (tid < 128) {
        int r = tid;
        float vv[8], m = -1e30f;
#pragma unroll
        for (int c = 0; c < 8; c++) {
            vv[c] = pool[LG_OFF + r * 8 + c];
            m = fmaxf(m, vv[c]);
        }
        float s = 0.f;
#pragma unroll
        for (int c = 0; c < 8; c++) { vv[c] = expf(vv[c] - m); s += vv[c]; }
        float inv = 1.0f / s;
        float4 o0 = make_float4(vv[0] * inv, vv[1] * inv, vv[2] * inv, vv[3] * inv);
        float4 o1 = make_float4(vv[4] * inv, vv[5] * inv, vv[6] * inv, vv[7] * inv);
        *reinterpret_cast<float4*>(out + (size_t)(m0 + r) * 8)     = o0;
        *reinterpret_cast<float4*>(out + (size_t)(m0 + r) * 8 + 4) = o1;
    }
}

// ---------------- launch ----------------
extern "C" void kernel_launch(void* const* d_in, const int* in_sizes, int n_in,
                              void* d_out, int out_size) {
    const float* x   = (const float*)d_in[0];
    const float* adj = (const float*)d_in[1];
    const float* Wp  = (const float*)d_in[2];
    const float* W1  = (const float*)d_in[3];
    const float* b1  = (const float*)d_in[4];
    const float* W2  = (const float*)d_in[5];
    const float* b2  = (const float*)d_in[6];
    const float* W3  = (const float*)d_in[7];
    const float* b3  = (const float*)d_in[8];
    float* out = (float*)d_out;

    const int psm = 4 * P_AST * 4;                  // 40960
    const int zsm = Z_SMEM_FLOATS * 4;              // 167424
    cudaFuncSetAttribute(p2_yT, cudaFuncAttributeMaxDynamicSharedMemorySize, psm);
    cudaFuncSetAttribute(p3_xp, cudaFuncAttributeMaxDynamicSharedMemorySize, psm);
    cudaFuncSetAttribute(gemm_z, cudaFuncAttributeMaxDynamicSharedMemorySize, zsm);

    convert_x<<<4096, 256>>>(x);
    convert_w<<<256, 256>>>(Wp);
    p2_yT<<<128, 256, psm>>>();
    p3_xp<<<128, 256, psm>>>();
    gemm_z<<<128, 512, zsm>>>(adj, W1, b1, W2, b2, W3, b3, out);
}